// round 4
// baseline (speedup 1.0000x reference)
#include <cuda_runtime.h>
#include <cuda_bf16.h>
#include <cstdint>

#define TT 128
#define BB 512
#define DD 512
#define OO 10

// ---------------- device scratch ----------------
static __device__ float          g_Y[TT * BB * DD];       // cur1 pre-BN [t][b][d]
static __device__ __nv_bfloat16  g_W1s[3][DD * DD];       // W1 bf16 limbs, [n][k]
static __device__ __nv_bfloat16  g_As[3][TT * BB * DD];   // A=(mask*data) bf16 limbs, [t*B+b][k]
static __device__ float          g_mean[TT * DD];
static __device__ float          g_rstd[TT * DD];
static __device__ unsigned       g_spk[TT * BB * (DD / 32)];
static __device__ float          g_cur2[TT * BB * OO];

// ---------------- helpers ----------------
__device__ __forceinline__ uint32_t smem_u32(const void* p) {
    uint32_t a;
    asm("{ .reg .u64 t; cvta.to.shared.u64 t, %1; cvt.u32.u64 %0, t; }"
        : "=r"(a) : "l"(p));
    return a;
}
#define SWZ128(off) ((off) ^ (((off) >> 3) & 0x70))

__device__ __forceinline__ void ldsm_x4(uint32_t* r, uint32_t addr) {
    asm volatile("ldmatrix.sync.aligned.m8n8.x4.shared.b16 {%0,%1,%2,%3}, [%4];"
                 : "=r"(r[0]), "=r"(r[1]), "=r"(r[2]), "=r"(r[3]) : "r"(addr));
}
__device__ __forceinline__ void mma16816(float* c, const uint32_t* a,
                                         uint32_t b0, uint32_t b1) {
    asm volatile(
        "mma.sync.aligned.m16n8k16.row.col.f32.bf16.bf16.f32 "
        "{%0,%1,%2,%3}, {%4,%5,%6,%7}, {%8,%9}, {%0,%1,%2,%3};"
        : "+f"(c[0]), "+f"(c[1]), "+f"(c[2]), "+f"(c[3])
        : "r"(a[0]), "r"(a[1]), "r"(a[2]), "r"(a[3]), "r"(b0), "r"(b1));
}

// pack two floats -> bf16x2 {arg0 -> low half, arg1 -> high half}
__device__ __forceinline__ uint32_t pkbf(float lo, float hi) {
    uint32_t r;
    asm("cvt.rn.bf16x2.f32 %0, %1, %2;" : "=r"(r) : "f"(hi), "f"(lo));
    return r;
}
__device__ __forceinline__ float lo_f(uint32_t v) { return __uint_as_float(v << 16); }
__device__ __forceinline__ float hi_f(uint32_t v) { return __uint_as_float(v & 0xffff0000u); }

// ---------------- W1 -> 3 bf16 limbs ----------------
__global__ void k_split(const float* __restrict__ W1) {
    int i = blockIdx.x * 256 + threadIdx.x;  // 262144
    float a = W1[i];
    __nv_bfloat16 h = __float2bfloat16(a);
    float r1 = a - __bfloat162float(h);
    __nv_bfloat16 m = __float2bfloat16(r1);
    float r2 = r1 - __bfloat162float(m);
    __nv_bfloat16 l = __float2bfloat16(r2);
    g_W1s[0][i] = h; g_W1s[1][i] = m; g_W1s[2][i] = l;
}

// ---------------- A = mask*data -> 3 bf16 limbs, row-major [t*B+b][k] -------
__global__ void k_convA(const float* __restrict__ data,
                        const float* __restrict__ mask) {
    int id = blockIdx.x * 256 + threadIdx.x;   // 8,388,608 = 65536 rows * 128 quads
    int r = id >> 7;                            // row = t*512 + b
    int kq = (id & 127) * 4;
    int t = r >> 9, b = r & 511;
    float4 dv = *(const float4*)(data + ((size_t)b * TT + t) * DD + kq);
    float4 mv = *(const float4*)(mask + ((size_t)t * BB + b) * DD + kq);
    float a0 = dv.x * mv.x, a1 = dv.y * mv.y;
    float a2 = dv.z * mv.z, a3 = dv.w * mv.w;
    uint32_t h01 = pkbf(a0, a1), h23 = pkbf(a2, a3);
    float q0 = a0 - lo_f(h01), q1 = a1 - hi_f(h01);
    float q2 = a2 - lo_f(h23), q3 = a3 - hi_f(h23);
    uint32_t m01 = pkbf(q0, q1), m23 = pkbf(q2, q3);
    float w0 = q0 - lo_f(m01), w1 = q1 - hi_f(m01);
    float w2 = q2 - lo_f(m23), w3 = q3 - hi_f(m23);
    uint32_t l01 = pkbf(w0, w1), l23 = pkbf(w2, w3);
    size_t o = (size_t)r * DD + kq;
    *(uint2*)(g_As[0] + o) = make_uint2(h01, h23);
    *(uint2*)(g_As[1] + o) = make_uint2(m01, m23);
    *(uint2*)(g_As[2] + o) = make_uint2(l01, l23);
}

// ---------------- BF16x9 split GEMM via mma.sync, split accumulators --------
// Y[r][n] = sum_k A[r][k] * W1[n][k]; CTA tile 128(M) x 64(N), K-chunk 64.
// Warp grid 4(m) x 2(n), warp tile 32x32.
#define TILE_A 16384   // 128 rows x 128B
#define TILE_W 8192    // 64 rows x 128B
#define SMEM_DYN (1024 + 3 * TILE_A + 3 * TILE_W)

__global__ __launch_bounds__(256) void k_gemm() {
    extern __shared__ char smem[];
    const uint32_t s0 = smem_u32(smem);
    const uint32_t base = (s0 + 1023u) & ~1023u;
    char* const smc = smem + (base - s0);
    const uint32_t wbase = base + 3 * TILE_A;

    const int tid = threadIdx.x;
    const int wid = tid >> 5;
    const int lane = tid & 31;

    const int n0 = blockIdx.x * 64;
    const int r0 = blockIdx.y * 128;

    // staging coords
    const int arow = tid >> 1, akh = (tid & 1) * 32;       // A: 32 bf16/thread/split
    const int brow = tid >> 2, bkq = (tid & 3) * 16;       // W: 16 bf16/thread/split
    const uint32_t arowb = (uint32_t)arow * 128u;
    const uint32_t browb = (uint32_t)brow * 128u;

    // warp tile origin
    const int wm0 = (wid & 3) * 32;
    const int wn0 = (wid >> 2) * 32;

    // ldmatrix lane bases (x4)
    const uint32_t a_row = (uint32_t)(wm0 + (lane & 15));
    const uint32_t a_koff = (uint32_t)((lane >> 4) * 8);
    const uint32_t b_row = (uint32_t)(wn0 + ((lane >> 4) << 3) + (lane & 7));
    const uint32_t b_koff = (uint32_t)(((lane >> 3) & 1) * 8);

    float C1[2][4][4], C2[2][4][4];
    #pragma unroll
    for (int mf = 0; mf < 2; mf++)
        #pragma unroll
        for (int nf = 0; nf < 4; nf++)
            #pragma unroll
            for (int q = 0; q < 4; q++) { C1[mf][nf][q] = 0.f; C2[mf][nf][q] = 0.f; }

    for (int kt = 0; kt < DD; kt += 64) {
        __syncthreads();
        // stage A limbs (bf16, pre-converted)
        #pragma unroll
        for (int s = 0; s < 3; s++) {
            const __nv_bfloat16* ap = g_As[s] + (size_t)(r0 + arow) * DD + kt + akh;
            #pragma unroll
            for (int j = 0; j < 4; j++) {
                uint4 v = *(const uint4*)(ap + j * 8);
                *(uint4*)(smc + s * TILE_A +
                          SWZ128(arowb + (uint32_t)(akh + j * 8) * 2u)) = v;
            }
        }
        // stage W limbs
        #pragma unroll
        for (int s = 0; s < 3; s++) {
            const __nv_bfloat16* wp = g_W1s[s] + (size_t)(n0 + brow) * DD + kt + bkq;
            #pragma unroll
            for (int j = 0; j < 2; j++) {
                uint4 v = *(const uint4*)(wp + j * 8);
                *(uint4*)(smc + 3 * TILE_A + s * TILE_W +
                          SWZ128(browb + (uint32_t)(bkq + j * 8) * 2u)) = v;
            }
        }
        __syncthreads();

        #pragma unroll
        for (int kk = 0; kk < 4; kk++) {
            uint32_t Af[3][2][4], Bf[3][2][4];
            #pragma unroll
            for (int s = 0; s < 3; s++) {
                #pragma unroll
                for (int mf = 0; mf < 2; mf++)
                    ldsm_x4(Af[s][mf], base + s * TILE_A +
                            SWZ128((a_row + mf * 16) * 128u + (kk * 16 + a_koff) * 2u));
                #pragma unroll
                for (int g = 0; g < 2; g++)
                    ldsm_x4(Bf[s][g], wbase + s * TILE_W +
                            SWZ128((b_row + g * 16) * 128u + (kk * 16 + b_koff) * 2u));
            }
#define PROD(sa, sb, Cc)                                                        \
            _Pragma("unroll")                                                   \
            for (int mf = 0; mf < 2; mf++)                                      \
                _Pragma("unroll")                                               \
                for (int g = 0; g < 2; g++) {                                   \
                    mma16816(Cc[mf][g * 2],     Af[sa][mf], Bf[sb][g][0], Bf[sb][g][1]); \
                    mma16816(Cc[mf][g * 2 + 1], Af[sa][mf], Bf[sb][g][2], Bf[sb][g][3]); \
                }
            PROD(0, 0, C1);            // main term, own accumulator
            PROD(0, 1, C2); PROD(1, 0, C2); PROD(1, 1, C2);
            PROD(0, 2, C2); PROD(2, 0, C2); PROD(1, 2, C2);
            PROD(2, 1, C2); PROD(2, 2, C2);
#undef PROD
        }
    }

    // epilogue: y = C1 + C2
    #pragma unroll
    for (int mf = 0; mf < 2; mf++) {
        int rbase = r0 + wm0 + mf * 16 + (lane >> 2);
        #pragma unroll
        for (int nf = 0; nf < 4; nf++) {
            int col = n0 + wn0 + nf * 8 + (lane & 3) * 2;
            *(float2*)(g_Y + (size_t)rbase * DD + col) =
                make_float2(C1[mf][nf][0] + C2[mf][nf][0],
                            C1[mf][nf][1] + C2[mf][nf][1]);
            *(float2*)(g_Y + (size_t)(rbase + 8) * DD + col) =
                make_float2(C1[mf][nf][2] + C2[mf][nf][2],
                            C1[mf][nf][3] + C2[mf][nf][3]);
        }
    }
}

// ---------------- BN stats (two-pass, matches reference rounding) -----------
__global__ void k_stats() {
    int idx = blockIdx.x * 256 + threadIdx.x;  // t*512 + d
    int t = idx >> 9, d = idx & 511;
    const float* col = g_Y + (size_t)t * BB * DD + d;
    float s = 0.f;
    for (int b = 0; b < BB; b++) s += col[(size_t)b * DD];
    float mean = s * (1.0f / BB);
    float v = 0.f;
    for (int b = 0; b < BB; b++) {
        float x = col[(size_t)b * DD] - mean;
        v += x * x;
    }
    float vpe = v * (1.0f / BB) + 1e-5f;
    g_mean[idx] = mean;
    g_rstd[idx] = (float)(1.0 / sqrt((double)vpe));
}

// ---------------- layer-1 membrane scan ----------------
__global__ void k_scan1(const float* __restrict__ gamma,
                        const float* __restrict__ beta) {
    int id = blockIdx.x * 256 + threadIdx.x;  // b*512 + d
    int b = id >> 9, d = id & 511;
    int lane = threadIdx.x & 31;
    float g = gamma[d], be = beta[d];
    float mem = 0.f, spk = 0.f;
    const float* yp = g_Y + (size_t)b * DD + d;
    unsigned* sp = g_spk + (size_t)b * 16 + (d >> 5);
    #pragma unroll 2
    for (int t0 = 0; t0 < TT; t0 += 4) {
        float y[4], mn[4], rs[4];
        #pragma unroll
        for (int i = 0; i < 4; i++) {
            y[i]  = yp[(size_t)(t0 + i) * BB * DD];
            mn[i] = g_mean[(t0 + i) * DD + d];
            rs[i] = g_rstd[(t0 + i) * DD + d];
        }
        #pragma unroll
        for (int i = 0; i < 4; i++) {
            float cur = g * (y[i] - mn[i]) * rs[i] + be;
            mem = 0.5f * mem + cur - spk;
            spk = (mem - 1.0f) > 0.f ? 1.0f : 0.0f;
            unsigned bal = __ballot_sync(0xffffffffu, spk != 0.f);
            if (lane == 0) sp[(size_t)(t0 + i) * BB * 16] = bal;
        }
    }
}

// ---------------- layer 2: cur2 = spk1 @ W2^T + b2 ----------------
__global__ __launch_bounds__(256) void k_layer2(const float* __restrict__ W2,
                                                const float* __restrict__ b2) {
    int r = blockIdx.x * 8 + (threadIdx.x >> 5);
    int lane = threadIdx.x & 31;
    const unsigned* sp = g_spk + (size_t)r * 16;
    float acc[10];
    #pragma unroll
    for (int o = 0; o < 10; o++) acc[o] = 0.f;
    #pragma unroll
    for (int j = 0; j < 16; j++) {
        unsigned w = sp[j];
        float s = ((w >> lane) & 1u) ? 1.0f : 0.0f;
        int d = j * 32 + lane;
        #pragma unroll
        for (int o = 0; o < 10; o++) acc[o] += s * W2[o * DD + d];
    }
    #pragma unroll
    for (int o = 0; o < 10; o++) {
        #pragma unroll
        for (int off = 16; off; off >>= 1)
            acc[o] += __shfl_xor_sync(0xffffffffu, acc[o], off);
    }
    if (lane == 0) {
        float* out = g_cur2 + (size_t)r * 10;
        #pragma unroll
        for (int o = 0; o < 10; o++) out[o] = acc[o] + b2[o];
    }
}

// ---------------- layer-2 membrane scan + output ----------------
__global__ void k_scan2(float* __restrict__ out) {
    int id = blockIdx.x * 256 + threadIdx.x;
    if (id >= BB * OO) return;
    int b = id / 10, o = id - b * 10;
    float mem = 0.f, spk = 0.f;
    for (int t = 0; t < TT; t++) {
        float c = g_cur2[((size_t)t * BB + b) * 10 + o];
        mem = 0.5f * mem + c - spk;
        spk = (mem - 1.0f) > 0.f ? 1.0f : 0.0f;
        out[((size_t)t * BB + b) * 10 + o] = spk;
    }
}

extern "C" void kernel_launch(void* const* d_in, const int* in_sizes, int n_in,
                              void* d_out, int out_size) {
    const float* data  = (const float*)d_in[0];  // [B,T,D]
    const float* mask  = (const float*)d_in[1];  // [T,B,D]
    const float* W1    = (const float*)d_in[2];  // [D,D]
    // d_in[3] = b1: cancels exactly under BatchNorm mean subtraction
    const float* gamma = (const float*)d_in[4];
    const float* beta  = (const float*)d_in[5];
    const float* W2    = (const float*)d_in[6];  // [O,D]
    const float* b2    = (const float*)d_in[7];
    float* out = (float*)d_out;                  // [T,B,O]

    cudaFuncSetAttribute(k_gemm, cudaFuncAttributeMaxDynamicSharedMemorySize, SMEM_DYN);

    k_split<<<1024, 256>>>(W1);
    k_convA<<<32768, 256>>>(data, mask);
    k_gemm<<<dim3(8, 512), 256, SMEM_DYN>>>();
    k_stats<<<256, 256>>>();
    k_scan1<<<1024, 256>>>(gamma, beta);
    k_layer2<<<8192, 256>>>(W2, b2);
    k_scan2<<<20, 256>>>(out);
}

// round 5
// speedup vs baseline: 1.2630x; 1.2630x over previous
#include <cuda_runtime.h>
#include <cuda_bf16.h>
#include <cstdint>

#define TT 128
#define BB 512
#define DD 512
#define OO 10

// ---------------- device scratch ----------------
static __device__ float          g_Y[TT * BB * DD];       // cur1 pre-BN [t][b][d]
static __device__ __nv_bfloat16  g_W1s[3][DD * DD];       // W1 bf16 limbs, [n][k]
static __device__ __nv_bfloat16  g_As[3][TT * BB * DD];   // A=(mask*data) limbs, [t*B+b][k]
static __device__ float          g_mean[TT * DD];
static __device__ float          g_rstd[TT * DD];
static __device__ unsigned       g_spk[TT * BB * (DD / 32)];
static __device__ float          g_cur2[TT * BB * OO];

// ---------------- helpers ----------------
__device__ __forceinline__ uint32_t smem_u32(const void* p) {
    uint32_t a;
    asm("{ .reg .u64 t; cvta.to.shared.u64 t, %1; cvt.u32.u64 %0, t; }"
        : "=r"(a) : "l"(p));
    return a;
}
#define SWZ128(off) ((off) ^ (((off) >> 3) & 0x70))

__device__ __forceinline__ void cp16(uint32_t dst, const void* src) {
    asm volatile("cp.async.cg.shared.global [%0], [%1], 16;"
                 :: "r"(dst), "l"(src) : "memory");
}
#define CP_COMMIT() asm volatile("cp.async.commit_group;" ::: "memory")
#define CP_WAIT(n)  asm volatile("cp.async.wait_group %0;" :: "n"(n) : "memory")

__device__ __forceinline__ void ldsm_x4(uint32_t* r, uint32_t addr) {
    asm volatile("ldmatrix.sync.aligned.m8n8.x4.shared.b16 {%0,%1,%2,%3}, [%4];"
                 : "=r"(r[0]), "=r"(r[1]), "=r"(r[2]), "=r"(r[3]) : "r"(addr));
}
__device__ __forceinline__ void mma16816(float* c, const uint32_t* a,
                                         uint32_t b0, uint32_t b1) {
    asm volatile(
        "mma.sync.aligned.m16n8k16.row.col.f32.bf16.bf16.f32 "
        "{%0,%1,%2,%3}, {%4,%5,%6,%7}, {%8,%9}, {%0,%1,%2,%3};"
        : "+f"(c[0]), "+f"(c[1]), "+f"(c[2]), "+f"(c[3])
        : "r"(a[0]), "r"(a[1]), "r"(a[2]), "r"(a[3]), "r"(b0), "r"(b1));
}

// pack two floats -> bf16x2
__device__ __forceinline__ uint32_t pkbf(float lo, float hi) {
    uint32_t r;
    asm("cvt.rn.bf16x2.f32 %0, %1, %2;" : "=r"(r) : "f"(hi), "f"(lo));
    return r;
}
__device__ __forceinline__ float lo_f(uint32_t v) { return __uint_as_float(v << 16); }
__device__ __forceinline__ float hi_f(uint32_t v) { return __uint_as_float(v & 0xffff0000u); }

// ---------------- W1 -> 3 bf16 limbs (exact split: 8+8+8 >= 24 bits) --------
__global__ void k_split(const float* __restrict__ W1) {
    int i = blockIdx.x * 256 + threadIdx.x;  // 262144
    float a = W1[i];
    __nv_bfloat16 h = __float2bfloat16(a);
    float r1 = a - __bfloat162float(h);
    __nv_bfloat16 m = __float2bfloat16(r1);
    float r2 = r1 - __bfloat162float(m);
    __nv_bfloat16 l = __float2bfloat16(r2);
    g_W1s[0][i] = h; g_W1s[1][i] = m; g_W1s[2][i] = l;
}

// ---------------- A = mask*data -> 3 bf16 limbs, row-major [t*B+b][k] -------
__global__ void k_convA(const float* __restrict__ data,
                        const float* __restrict__ mask) {
    int id = blockIdx.x * 256 + threadIdx.x;   // 8,388,608
    int r = id >> 7;                            // row = t*512 + b
    int kq = (id & 127) * 4;
    int t = r >> 9, b = r & 511;
    float4 dv = *(const float4*)(data + ((size_t)b * TT + t) * DD + kq);
    float4 mv = *(const float4*)(mask + ((size_t)t * BB + b) * DD + kq);
    float a0 = dv.x * mv.x, a1 = dv.y * mv.y;
    float a2 = dv.z * mv.z, a3 = dv.w * mv.w;
    uint32_t h01 = pkbf(a0, a1), h23 = pkbf(a2, a3);
    float q0 = a0 - lo_f(h01), q1 = a1 - hi_f(h01);
    float q2 = a2 - lo_f(h23), q3 = a3 - hi_f(h23);
    uint32_t m01 = pkbf(q0, q1), m23 = pkbf(q2, q3);
    float w0 = q0 - lo_f(m01), w1 = q1 - hi_f(m01);
    float w2 = q2 - lo_f(m23), w3 = q3 - hi_f(m23);
    uint32_t l01 = pkbf(w0, w1), l23 = pkbf(w2, w3);
    size_t o = (size_t)r * DD + kq;
    *(uint2*)(g_As[0] + o) = make_uint2(h01, h23);
    *(uint2*)(g_As[1] + o) = make_uint2(m01, m23);
    *(uint2*)(g_As[2] + o) = make_uint2(l01, l23);
}

// ---------------- BF16x8 split GEMM: cp.async double-buffered pipeline ------
// Y[r][n] = sum_k A[r][k] * W1[n][k]; CTA 128(M) x 64(N), K-chunk 64.
// Warp grid 4(m) x 2(n), warp tile 32x32. Products: a1b1 -> C1;
// {a1b2,a2b1,a2b2,a1b3,a3b1,a2b3,a3b2} -> C2 (a3b3 dropped: <=3e-8 abs).
#define TILE_A 16384   // 128 rows x 128B per limb
#define TILE_W 8192    // 64 rows x 128B per limb
#define BUF_SZ (3 * TILE_A + 3 * TILE_W)     // 73728
#define SMEM_DYN (1024 + 2 * BUF_SZ)

__global__ __launch_bounds__(256, 1) void k_gemm() {
    extern __shared__ char smem[];
    const uint32_t s0 = smem_u32(smem);
    const uint32_t base = (s0 + 1023u) & ~1023u;

    const int tid = threadIdx.x;
    const int wid = tid >> 5;
    const int lane = tid & 31;

    const int n0 = blockIdx.x * 64;
    const int r0 = blockIdx.y * 128;

    // staging coords (cp.async, 16B each)
    const int arow = tid >> 1;
    const uint32_t aoffb = (uint32_t)((tid & 1) * 64);   // byte offset base in row
    const int wrow = tid >> 2;
    const uint32_t woffb = (uint32_t)((tid & 3) * 32);

    const __nv_bfloat16* aptr[3];
    const __nv_bfloat16* wptr[3];
    #pragma unroll
    for (int s = 0; s < 3; s++) {
        aptr[s] = g_As[s] + (size_t)(r0 + arow) * DD + (aoffb >> 1);
        wptr[s] = g_W1s[s] + (size_t)(n0 + wrow) * DD + (woffb >> 1);
    }
    const uint32_t arowb = (uint32_t)arow * 128u;
    const uint32_t wrowb = (uint32_t)wrow * 128u;

#define STAGE(kt, buf)                                                          \
    do {                                                                        \
        uint32_t bb = base + (buf) * BUF_SZ;                                    \
        _Pragma("unroll")                                                       \
        for (int s = 0; s < 3; s++) {                                           \
            _Pragma("unroll")                                                   \
            for (int j = 0; j < 4; j++) {                                       \
                uint32_t ob = aoffb + j * 16;                                   \
                cp16(bb + s * TILE_A + SWZ128(arowb + ob),                      \
                     aptr[s] + (kt) + (ob >> 1) - (aoffb >> 1));                \
            }                                                                   \
            _Pragma("unroll")                                                   \
            for (int j = 0; j < 2; j++) {                                       \
                uint32_t ob = woffb + j * 16;                                   \
                cp16(bb + 3 * TILE_A + s * TILE_W + SWZ128(wrowb + ob),         \
                     wptr[s] + (kt) + (ob >> 1) - (woffb >> 1));                \
            }                                                                   \
        }                                                                       \
    } while (0)

    // warp tile + ldmatrix lane bases
    const int wm0 = (wid & 3) * 32;
    const int wn0 = (wid >> 2) * 32;
    const uint32_t a_row = (uint32_t)(wm0 + (lane & 15));
    const uint32_t a_koff = (uint32_t)((lane >> 4) * 8);
    const uint32_t b_row = (uint32_t)(wn0 + ((lane >> 4) << 3) + (lane & 7));
    const uint32_t b_koff = (uint32_t)(((lane >> 3) & 1) * 8);

    float C1[2][4][4], C2[2][4][4];
    #pragma unroll
    for (int mf = 0; mf < 2; mf++)
        #pragma unroll
        for (int nf = 0; nf < 4; nf++)
            #pragma unroll
            for (int q = 0; q < 4; q++) { C1[mf][nf][q] = 0.f; C2[mf][nf][q] = 0.f; }

    STAGE(0, 0);
    CP_COMMIT();

    for (int c = 0; c < 8; c++) {
        const int buf = c & 1;
        if (c < 7) {
            STAGE((c + 1) * 64, buf ^ 1);
            CP_COMMIT();
            CP_WAIT(1);
        } else {
            CP_WAIT(0);
        }
        __syncthreads();

        const uint32_t ab = base + buf * BUF_SZ;
        const uint32_t wb = ab + 3 * TILE_A;
        #pragma unroll
        for (int kk = 0; kk < 4; kk++) {
            uint32_t Af[3][2][4], Bf[3][2][4];
            #pragma unroll
            for (int s = 0; s < 3; s++) {
                #pragma unroll
                for (int mf = 0; mf < 2; mf++)
                    ldsm_x4(Af[s][mf], ab + s * TILE_A +
                            SWZ128((a_row + mf * 16) * 128u + (kk * 16 + a_koff) * 2u));
                #pragma unroll
                for (int g = 0; g < 2; g++)
                    ldsm_x4(Bf[s][g], wb + s * TILE_W +
                            SWZ128((b_row + g * 16) * 128u + (kk * 16 + b_koff) * 2u));
            }
#define PROD(sa, sb, Cc)                                                        \
            _Pragma("unroll")                                                   \
            for (int mf = 0; mf < 2; mf++)                                      \
                _Pragma("unroll")                                               \
                for (int g = 0; g < 2; g++) {                                   \
                    mma16816(Cc[mf][g * 2],     Af[sa][mf], Bf[sb][g][0], Bf[sb][g][1]); \
                    mma16816(Cc[mf][g * 2 + 1], Af[sa][mf], Bf[sb][g][2], Bf[sb][g][3]); \
                }
            PROD(0, 0, C1);
            PROD(0, 1, C2); PROD(1, 0, C2); PROD(1, 1, C2);
            PROD(0, 2, C2); PROD(2, 0, C2);
            PROD(1, 2, C2); PROD(2, 1, C2);
#undef PROD
        }
        __syncthreads();
    }

    // epilogue: y = C1 + C2
    #pragma unroll
    for (int mf = 0; mf < 2; mf++) {
        int rbase = r0 + wm0 + mf * 16 + (lane >> 2);
        #pragma unroll
        for (int nf = 0; nf < 4; nf++) {
            int col = n0 + wn0 + nf * 8 + (lane & 3) * 2;
            *(float2*)(g_Y + (size_t)rbase * DD + col) =
                make_float2(C1[mf][nf][0] + C2[mf][nf][0],
                            C1[mf][nf][1] + C2[mf][nf][1]);
            *(float2*)(g_Y + (size_t)(rbase + 8) * DD + col) =
                make_float2(C1[mf][nf][2] + C2[mf][nf][2],
                            C1[mf][nf][3] + C2[mf][nf][3]);
        }
    }
}

// ---------------- BN stats (two-pass, UNCHANGED numerics) ------------------
__global__ void k_stats() {
    int idx = blockIdx.x * 256 + threadIdx.x;  // t*512 + d
    int t = idx >> 9, d = idx & 511;
    const float* col = g_Y + (size_t)t * BB * DD + d;
    float s = 0.f;
    for (int b = 0; b < BB; b++) s += col[(size_t)b * DD];
    float mean = s * (1.0f / BB);
    float v = 0.f;
    for (int b = 0; b < BB; b++) {
        float x = col[(size_t)b * DD] - mean;
        v += x * x;
    }
    float vpe = v * (1.0f / BB) + 1e-5f;
    g_mean[idx] = mean;
    g_rstd[idx] = (float)(1.0 / sqrt((double)vpe));
}

// ---------------- layer-1 membrane scan ----------------
__global__ void k_scan1(const float* __restrict__ gamma,
                        const float* __restrict__ beta) {
    int id = blockIdx.x * 256 + threadIdx.x;  // b*512 + d
    int b = id >> 9, d = id & 511;
    int lane = threadIdx.x & 31;
    float g = gamma[d], be = beta[d];
    float mem = 0.f, spk = 0.f;
    const float* yp = g_Y + (size_t)b * DD + d;
    unsigned* sp = g_spk + (size_t)b * 16 + (d >> 5);
    for (int t0 = 0; t0 < TT; t0 += 8) {
        float y[8], mn[8], rs[8];
        #pragma unroll
        for (int i = 0; i < 8; i++) {
            y[i]  = yp[(size_t)(t0 + i) * BB * DD];
            mn[i] = g_mean[(t0 + i) * DD + d];
            rs[i] = g_rstd[(t0 + i) * DD + d];
        }
        #pragma unroll
        for (int i = 0; i < 8; i++) {
            float cur = g * (y[i] - mn[i]) * rs[i] + be;
            mem = 0.5f * mem + cur - spk;
            spk = (mem - 1.0f) > 0.f ? 1.0f : 0.0f;
            unsigned bal = __ballot_sync(0xffffffffu, spk != 0.f);
            if (lane == 0) sp[(size_t)(t0 + i) * BB * 16] = bal;
        }
    }
}

// ---------------- layer 2: cur2 = spk1 @ W2^T + b2 ----------------
__global__ __launch_bounds__(256) void k_layer2(const float* __restrict__ W2,
                                                const float* __restrict__ b2) {
    int r = blockIdx.x * 8 + (threadIdx.x >> 5);
    int lane = threadIdx.x & 31;
    const unsigned* sp = g_spk + (size_t)r * 16;
    float acc[10];
    #pragma unroll
    for (int o = 0; o < 10; o++) acc[o] = 0.f;
    #pragma unroll
    for (int j = 0; j < 16; j++) {
        unsigned w = sp[j];
        float s = ((w >> lane) & 1u) ? 1.0f : 0.0f;
        int d = j * 32 + lane;
        #pragma unroll
        for (int o = 0; o < 10; o++) acc[o] += s * W2[o * DD + d];
    }
    #pragma unroll
    for (int o = 0; o < 10; o++) {
        #pragma unroll
        for (int off = 16; off; off >>= 1)
            acc[o] += __shfl_xor_sync(0xffffffffu, acc[o], off);
    }
    if (lane == 0) {
        float* out = g_cur2 + (size_t)r * 10;
        #pragma unroll
        for (int o = 0; o < 10; o++) out[o] = acc[o] + b2[o];
    }
}

// ---------------- layer-2 membrane scan + output ----------------
__global__ void k_scan2(float* __restrict__ out) {
    int id = blockIdx.x * 256 + threadIdx.x;
    if (id >= BB * OO) return;
    int b = id / 10, o = id - b * 10;
    float mem = 0.f, spk = 0.f;
    for (int t = 0; t < TT; t++) {
        float c = g_cur2[((size_t)t * BB + b) * 10 + o];
        mem = 0.5f * mem + c - spk;
        spk = (mem - 1.0f) > 0.f ? 1.0f : 0.0f;
        out[((size_t)t * BB + b) * 10 + o] = spk;
    }
}

extern "C" void kernel_launch(void* const* d_in, const int* in_sizes, int n_in,
                              void* d_out, int out_size) {
    const float* data  = (const float*)d_in[0];  // [B,T,D]
    const float* mask  = (const float*)d_in[1];  // [T,B,D]
    const float* W1    = (const float*)d_in[2];  // [D,D]
    // d_in[3] = b1: cancels exactly under BatchNorm mean subtraction
    const float* gamma = (const float*)d_in[4];
    const float* beta  = (const float*)d_in[5];
    const float* W2    = (const float*)d_in[6];  // [O,D]
    const float* b2    = (const float*)d_in[7];
    float* out = (float*)d_out;                  // [T,B,O]

    cudaFuncSetAttribute(k_gemm, cudaFuncAttributeMaxDynamicSharedMemorySize, SMEM_DYN);

    k_split<<<1024, 256>>>(W1);
    k_convA<<<32768, 256>>>(data, mask);
    k_gemm<<<dim3(8, 512), 256, SMEM_DYN>>>();
    k_stats<<<256, 256>>>();
    k_scan1<<<1024, 256>>>(gamma, beta);
    k_layer2<<<8192, 256>>>(W2, b2);
    k_scan2<<<20, 256>>>(out);
}

// round 6
// speedup vs baseline: 1.4151x; 1.1204x over previous
#include <cuda_runtime.h>
#include <cuda_bf16.h>
#include <cstdint>

#define TT 128
#define BB 512
#define DD 512
#define OO 10

// ---------------- device scratch ----------------
static __device__ float          g_Y[TT * BB * DD];       // cur1 pre-BN [t][b][d]
static __device__ __nv_bfloat16  g_W1s[3][DD * DD];       // W1 bf16 limbs, [n][k]
static __device__ __nv_bfloat16  g_As[3][TT * BB * DD];   // A=(mask*data) limbs, [t*B+b][k]
static __device__ float          g_mean[TT * DD];
static __device__ float          g_rstd[TT * DD];
static __device__ unsigned       g_spk[TT * BB * (DD / 32)];
static __device__ float          g_cur2[TT * BB * OO];

// ---------------- helpers ----------------
__device__ __forceinline__ uint32_t smem_u32(const void* p) {
    uint32_t a;
    asm("{ .reg .u64 t; cvta.to.shared.u64 t, %1; cvt.u32.u64 %0, t; }"
        : "=r"(a) : "l"(p));
    return a;
}
#define SWZ128(off) ((off) ^ (((off) >> 3) & 0x70))

__device__ __forceinline__ void cp16(uint32_t dst, const void* src) {
    asm volatile("cp.async.cg.shared.global [%0], [%1], 16;"
                 :: "r"(dst), "l"(src) : "memory");
}
#define CP_COMMIT() asm volatile("cp.async.commit_group;" ::: "memory")
#define CP_WAIT(n)  asm volatile("cp.async.wait_group %0;" :: "n"(n) : "memory")

__device__ __forceinline__ void ldsm_x4(uint32_t* r, uint32_t addr) {
    asm volatile("ldmatrix.sync.aligned.m8n8.x4.shared.b16 {%0,%1,%2,%3}, [%4];"
                 : "=r"(r[0]), "=r"(r[1]), "=r"(r[2]), "=r"(r[3]) : "r"(addr));
}
__device__ __forceinline__ void mma16816(float* c, const uint32_t* a,
                                         uint32_t b0, uint32_t b1) {
    asm volatile(
        "mma.sync.aligned.m16n8k16.row.col.f32.bf16.bf16.f32 "
        "{%0,%1,%2,%3}, {%4,%5,%6,%7}, {%8,%9}, {%0,%1,%2,%3};"
        : "+f"(c[0]), "+f"(c[1]), "+f"(c[2]), "+f"(c[3])
        : "r"(a[0]), "r"(a[1]), "r"(a[2]), "r"(a[3]), "r"(b0), "r"(b1));
}

// pack two floats -> bf16x2
__device__ __forceinline__ uint32_t pkbf(float lo, float hi) {
    uint32_t r;
    asm("cvt.rn.bf16x2.f32 %0, %1, %2;" : "=r"(r) : "f"(hi), "f"(lo));
    return r;
}
__device__ __forceinline__ float lo_f(uint32_t v) { return __uint_as_float(v << 16); }
__device__ __forceinline__ float hi_f(uint32_t v) { return __uint_as_float(v & 0xffff0000u); }

// ---------------- W1 -> 3 bf16 limbs (exact split: 8+8+8 >= 24 bits) --------
__global__ void k_split(const float* __restrict__ W1) {
    int i = blockIdx.x * 256 + threadIdx.x;  // 262144
    float a = W1[i];
    __nv_bfloat16 h = __float2bfloat16(a);
    float r1 = a - __bfloat162float(h);
    __nv_bfloat16 m = __float2bfloat16(r1);
    float r2 = r1 - __bfloat162float(m);
    __nv_bfloat16 l = __float2bfloat16(r2);
    g_W1s[0][i] = h; g_W1s[1][i] = m; g_W1s[2][i] = l;
}

// ---------------- A = mask*data -> 3 bf16 limbs (two launches) --------------
__global__ void k_convA(const float* __restrict__ data,
                        const float* __restrict__ mask, int base_id) {
    int id = base_id + blockIdx.x * 256 + threadIdx.x;
    int r = id >> 7;                            // row = t*512 + b
    int kq = (id & 127) * 4;
    int t = r >> 9, b = r & 511;
    float4 dv = *(const float4*)(data + ((size_t)b * TT + t) * DD + kq);
    float4 mv = *(const float4*)(mask + ((size_t)t * BB + b) * DD + kq);
    float a0 = dv.x * mv.x, a1 = dv.y * mv.y;
    float a2 = dv.z * mv.z, a3 = dv.w * mv.w;
    uint32_t h01 = pkbf(a0, a1), h23 = pkbf(a2, a3);
    float q0 = a0 - lo_f(h01), q1 = a1 - hi_f(h01);
    float q2 = a2 - lo_f(h23), q3 = a3 - hi_f(h23);
    uint32_t m01 = pkbf(q0, q1), m23 = pkbf(q2, q3);
    float w0 = q0 - lo_f(m01), w1 = q1 - hi_f(m01);
    float w2 = q2 - lo_f(m23), w3 = q3 - hi_f(m23);
    uint32_t l01 = pkbf(w0, w1), l23 = pkbf(w2, w3);
    size_t o = (size_t)r * DD + kq;
    *(uint2*)(g_As[0] + o) = make_uint2(h01, h23);
    *(uint2*)(g_As[1] + o) = make_uint2(m01, m23);
    *(uint2*)(g_As[2] + o) = make_uint2(l01, l23);
}

// ---------------- BF16x8 split GEMM, 2 CTAs/SM -------------------------------
// Y[r][n] = sum_k A[r][k]*W1[n][k]; CTA 64(M) x 64(N), K-chunk 64, dbl-buffered.
// Warp grid 4(m) x 2(n), warp tile 16x32. a1b1 -> C1; other 7 products -> C2
// (a3b3 dropped, <=3e-8 abs). Per-element FP op order identical to round 5.
#define TILE_L 8192    // 64 rows x 128B per limb (A and W identical shape)
#define BUF_SZ (6 * TILE_L)                  // 49152
#define SMEM_DYN (1024 + 2 * BUF_SZ)

__global__ __launch_bounds__(256, 2) void k_gemm() {
    extern __shared__ char smem[];
    const uint32_t s0 = smem_u32(smem);
    const uint32_t base = (s0 + 1023u) & ~1023u;

    const int tid = threadIdx.x;
    const int wid = tid >> 5;
    const int lane = tid & 31;

    const int n0 = blockIdx.x * 64;
    const int r0 = blockIdx.y * 64;

    // staging coords: 64 rows x 128B per limb; thread -> (row, 32B segment)
    const int srow = tid >> 2;
    const uint32_t soffb = (uint32_t)((tid & 3) * 32);   // byte offset in row
    const uint32_t srowb = (uint32_t)srow * 128u;

    const __nv_bfloat16* aptr[3];
    const __nv_bfloat16* wptr[3];
    #pragma unroll
    for (int s = 0; s < 3; s++) {
        aptr[s] = g_As[s] + (size_t)(r0 + srow) * DD + (soffb >> 1);
        wptr[s] = g_W1s[s] + (size_t)(n0 + srow) * DD + (soffb >> 1);
    }

#define STAGE(kt, buf)                                                          \
    do {                                                                        \
        uint32_t bb = base + (buf) * BUF_SZ;                                    \
        _Pragma("unroll")                                                       \
        for (int s = 0; s < 3; s++) {                                           \
            _Pragma("unroll")                                                   \
            for (int j = 0; j < 2; j++) {                                       \
                uint32_t ob = soffb + j * 16;                                   \
                cp16(bb + s * TILE_L + SWZ128(srowb + ob),                      \
                     aptr[s] + (kt) + j * 8);                                   \
                cp16(bb + (3 + s) * TILE_L + SWZ128(srowb + ob),                \
                     wptr[s] + (kt) + j * 8);                                   \
            }                                                                   \
        }                                                                       \
    } while (0)

    // warp tile + ldmatrix lane bases
    const int wm0 = (wid & 3) * 16;
    const int wn0 = (wid >> 2) * 32;
    const uint32_t a_row = (uint32_t)(wm0 + (lane & 15));
    const uint32_t a_koff = (uint32_t)((lane >> 4) * 8);
    const uint32_t b_row = (uint32_t)(wn0 + ((lane >> 4) << 3) + (lane & 7));
    const uint32_t b_koff = (uint32_t)(((lane >> 3) & 1) * 8);

    float C1[4][4], C2[4][4];
    #pragma unroll
    for (int nf = 0; nf < 4; nf++)
        #pragma unroll
        for (int q = 0; q < 4; q++) { C1[nf][q] = 0.f; C2[nf][q] = 0.f; }

    STAGE(0, 0);
    CP_COMMIT();

    for (int c = 0; c < 8; c++) {
        const int buf = c & 1;
        if (c < 7) {
            STAGE((c + 1) * 64, buf ^ 1);
            CP_COMMIT();
            CP_WAIT(1);
        } else {
            CP_WAIT(0);
        }
        __syncthreads();

        const uint32_t ab = base + buf * BUF_SZ;
        const uint32_t wb = ab + 3 * TILE_L;
        #pragma unroll
        for (int kk = 0; kk < 4; kk++) {
            uint32_t Af[3][4];
            #pragma unroll
            for (int s = 0; s < 3; s++)
                ldsm_x4(Af[s], ab + s * TILE_L +
                        SWZ128(a_row * 128u + (kk * 16 + a_koff) * 2u));

#define BLOAD(sb, Bf)                                                           \
            _Pragma("unroll")                                                   \
            for (int g = 0; g < 2; g++)                                         \
                ldsm_x4(Bf[g], wb + (sb) * TILE_L +                             \
                        SWZ128((b_row + g * 16) * 128u + (kk * 16 + b_koff) * 2u))
#define PROD(sa, Bf, Cc)                                                        \
            _Pragma("unroll")                                                   \
            for (int g = 0; g < 2; g++) {                                       \
                mma16816(Cc[g * 2],     Af[sa], Bf[g][0], Bf[g][1]);            \
                mma16816(Cc[g * 2 + 1], Af[sa], Bf[g][2], Bf[g][3]);            \
            }
            {
                uint32_t Bf[2][4];
                BLOAD(0, Bf);
                PROD(0, Bf, C1); PROD(1, Bf, C2); PROD(2, Bf, C2);
            }
            {
                uint32_t Bf[2][4];
                BLOAD(1, Bf);
                PROD(0, Bf, C2); PROD(1, Bf, C2); PROD(2, Bf, C2);
            }
            {
                uint32_t Bf[2][4];
                BLOAD(2, Bf);
                PROD(0, Bf, C2); PROD(1, Bf, C2);
            }
#undef PROD
#undef BLOAD
        }
        __syncthreads();
    }

    // epilogue: y = C1 + C2
    {
        int rbase = r0 + wm0 + (lane >> 2);
        #pragma unroll
        for (int nf = 0; nf < 4; nf++) {
            int col = n0 + wn0 + nf * 8 + (lane & 3) * 2;
            *(float2*)(g_Y + (size_t)rbase * DD + col) =
                make_float2(C1[nf][0] + C2[nf][0], C1[nf][1] + C2[nf][1]);
            *(float2*)(g_Y + (size_t)(rbase + 8) * DD + col) =
                make_float2(C1[nf][2] + C2[nf][2], C1[nf][3] + C2[nf][3]);
        }
    }
}

// ---------------- BN stats (two-pass, UNCHANGED numerics) ------------------
__global__ void k_stats() {
    int idx = blockIdx.x * 256 + threadIdx.x;  // t*512 + d
    int t = idx >> 9, d = idx & 511;
    const float* col = g_Y + (size_t)t * BB * DD + d;
    float s = 0.f;
    for (int b = 0; b < BB; b++) s += col[(size_t)b * DD];
    float mean = s * (1.0f / BB);
    float v = 0.f;
    for (int b = 0; b < BB; b++) {
        float x = col[(size_t)b * DD] - mean;
        v += x * x;
    }
    float vpe = v * (1.0f / BB) + 1e-5f;
    g_mean[idx] = mean;
    g_rstd[idx] = (float)(1.0 / sqrt((double)vpe));
}

// ---------------- layer-1 membrane scan ----------------
__global__ void k_scan1(const float* __restrict__ gamma,
                        const float* __restrict__ beta) {
    int id = blockIdx.x * 256 + threadIdx.x;  // b*512 + d
    int b = id >> 9, d = id & 511;
    int lane = threadIdx.x & 31;
    float g = gamma[d], be = beta[d];
    float mem = 0.f, spk = 0.f;
    const float* yp = g_Y + (size_t)b * DD + d;
    unsigned* sp = g_spk + (size_t)b * 16 + (d >> 5);
    for (int t0 = 0; t0 < TT; t0 += 8) {
        float y[8], mn[8], rs[8];
        #pragma unroll
        for (int i = 0; i < 8; i++) {
            y[i]  = yp[(size_t)(t0 + i) * BB * DD];
            mn[i] = g_mean[(t0 + i) * DD + d];
            rs[i] = g_rstd[(t0 + i) * DD + d];
        }
        #pragma unroll
        for (int i = 0; i < 8; i++) {
            float cur = g * (y[i] - mn[i]) * rs[i] + be;
            mem = 0.5f * mem + cur - spk;
            spk = (mem - 1.0f) > 0.f ? 1.0f : 0.0f;
            unsigned bal = __ballot_sync(0xffffffffu, spk != 0.f);
            if (lane == 0) sp[(size_t)(t0 + i) * BB * 16] = bal;
        }
    }
}

// ---------------- layer 2: cur2 = spk1 @ W2^T + b2 ----------------
__global__ __launch_bounds__(256) void k_layer2(const float* __restrict__ W2,
                                                const float* __restrict__ b2) {
    int r = blockIdx.x * 8 + (threadIdx.x >> 5);
    int lane = threadIdx.x & 31;
    const unsigned* sp = g_spk + (size_t)r * 16;
    float acc[10];
    #pragma unroll
    for (int o = 0; o < 10; o++) acc[o] = 0.f;
    #pragma unroll
    for (int j = 0; j < 16; j++) {
        unsigned w = sp[j];
        float s = ((w >> lane) & 1u) ? 1.0f : 0.0f;
        int d = j * 32 + lane;
        #pragma unroll
        for (int o = 0; o < 10; o++) acc[o] += s * W2[o * DD + d];
    }
    #pragma unroll
    for (int o = 0; o < 10; o++) {
        #pragma unroll
        for (int off = 16; off; off >>= 1)
            acc[o] += __shfl_xor_sync(0xffffffffu, acc[o], off);
    }
    if (lane == 0) {
        float* out = g_cur2 + (size_t)r * 10;
        #pragma unroll
        for (int o = 0; o < 10; o++) out[o] = acc[o] + b2[o];
    }
}

// ---------------- layer-2 membrane scan + output ----------------
__global__ void k_scan2(float* __restrict__ out) {
    int id = blockIdx.x * 256 + threadIdx.x;
    if (id >= BB * OO) return;
    int b = id / 10, o = id - b * 10;
    float mem = 0.f, spk = 0.f;
    for (int t = 0; t < TT; t++) {
        float c = g_cur2[((size_t)t * BB + b) * 10 + o];
        mem = 0.5f * mem + c - spk;
        spk = (mem - 1.0f) > 0.f ? 1.0f : 0.0f;
        out[((size_t)t * BB + b) * 10 + o] = spk;
    }
}

extern "C" void kernel_launch(void* const* d_in, const int* in_sizes, int n_in,
                              void* d_out, int out_size) {
    const float* data  = (const float*)d_in[0];  // [B,T,D]
    const float* mask  = (const float*)d_in[1];  // [T,B,D]
    const float* W1    = (const float*)d_in[2];  // [D,D]
    // d_in[3] = b1: cancels exactly under BatchNorm mean subtraction
    const float* gamma = (const float*)d_in[4];
    const float* beta  = (const float*)d_in[5];
    const float* W2    = (const float*)d_in[6];  // [O,D]
    const float* b2    = (const float*)d_in[7];
    float* out = (float*)d_out;                  // [T,B,O]

    cudaFuncSetAttribute(k_gemm, cudaFuncAttributeMaxDynamicSharedMemorySize, SMEM_DYN);

    // Launch order arranged so k_gemm is the 4th launch (ncu capture slot).
    k_split<<<1024, 256>>>(W1);
    k_convA<<<16384, 256>>>(data, mask, 0);
    k_convA<<<16384, 256>>>(data, mask, 16384 * 256);
    k_gemm<<<dim3(8, 1024), 256, SMEM_DYN>>>();
    k_stats<<<256, 256>>>();
    k_scan1<<<1024, 256>>>(gamma, beta);
    k_layer2<<<8192, 256>>>(W2, b2);
    k_scan2<<<20, 256>>>(out);
}

// round 7
// speedup vs baseline: 1.7595x; 1.2434x over previous
#include <cuda_runtime.h>
#include <cuda_fp16.h>
#include <cstdint>

#define TT 128
#define BB 512
#define DD 512
#define OO 10

#define SCL 4096.0f                 // 2^12 operand scale (exact)
#define DSCL 5.9604644775390625e-8f // 2^-24 descale (exact)

// ---------------- device scratch ----------------
static __device__ float     g_Y[TT * BB * DD];       // cur1 pre-BN [t][b][d]
static __device__ __half    g_W1s[3][DD * DD];       // W1*2^12 fp16 limbs, [n][k]
static __device__ __half    g_As[3][TT * BB * DD];   // (mask*data)*2^12 limbs, [t*B+b][k]
static __device__ float     g_mean[TT * DD];
static __device__ float     g_rstd[TT * DD];
static __device__ unsigned  g_spk[TT * BB * (DD / 32)];
static __device__ float     g_cur2[TT * BB * OO];

// ---------------- helpers ----------------
__device__ __forceinline__ uint32_t smem_u32(const void* p) {
    uint32_t a;
    asm("{ .reg .u64 t; cvta.to.shared.u64 t, %1; cvt.u32.u64 %0, t; }"
        : "=r"(a) : "l"(p));
    return a;
}
#define SWZ128(off) ((off) ^ (((off) >> 3) & 0x70))

__device__ __forceinline__ void cp16(uint32_t dst, const void* src) {
    asm volatile("cp.async.cg.shared.global [%0], [%1], 16;"
                 :: "r"(dst), "l"(src) : "memory");
}
#define CP_COMMIT() asm volatile("cp.async.commit_group;" ::: "memory")
#define CP_WAIT(n)  asm volatile("cp.async.wait_group %0;" :: "n"(n) : "memory")

__device__ __forceinline__ void ldsm_x4(uint32_t* r, uint32_t addr) {
    asm volatile("ldmatrix.sync.aligned.m8n8.x4.shared.b16 {%0,%1,%2,%3}, [%4];"
                 : "=r"(r[0]), "=r"(r[1]), "=r"(r[2]), "=r"(r[3]) : "r"(addr));
}
__device__ __forceinline__ void mma16816(float* c, const uint32_t* a,
                                         uint32_t b0, uint32_t b1) {
    asm volatile(
        "mma.sync.aligned.m16n8k16.row.col.f32.f16.f16.f32 "
        "{%0,%1,%2,%3}, {%4,%5,%6,%7}, {%8,%9}, {%0,%1,%2,%3};"
        : "+f"(c[0]), "+f"(c[1]), "+f"(c[2]), "+f"(c[3])
        : "r"(a[0]), "r"(a[1]), "r"(a[2]), "r"(a[3]), "r"(b0), "r"(b1));
}

// pack two floats -> half2 (RN); unpack halves back to float
__device__ __forceinline__ uint32_t pkh(float lo, float hi) {
    __half2 h = __floats2half2_rn(lo, hi);
    return *(uint32_t*)&h;
}
__device__ __forceinline__ float lo_h(uint32_t v) {
    __half2 h = *(__half2*)&v; return __low2float(h);
}
__device__ __forceinline__ float hi_h(uint32_t v) {
    __half2 h = *(__half2*)&v; return __high2float(h);
}

// ---------------- W1*2^12 -> 3 fp16 limbs (11+11+rest: exact to 2^-36 abs) --
__global__ void k_split(const float* __restrict__ W1) {
    int i = blockIdx.x * 256 + threadIdx.x;  // 262144
    float a = W1[i] * SCL;
    __half h = __float2half_rn(a);
    float r1 = a - __half2float(h);
    __half m = __float2half_rn(r1);
    float r2 = r1 - __half2float(m);
    __half l = __float2half_rn(r2);
    g_W1s[0][i] = h; g_W1s[1][i] = m; g_W1s[2][i] = l;
}

// ---------------- A = (mask*data)*2^12 -> 3 fp16 limbs (two launches) -------
__global__ void k_convA(const float* __restrict__ data,
                        const float* __restrict__ mask, int base_id) {
    int id = base_id + blockIdx.x * 256 + threadIdx.x;
    int r = id >> 7;                            // row = t*512 + b
    int kq = (id & 127) * 4;
    int t = r >> 9, b = r & 511;
    float4 dv = *(const float4*)(data + ((size_t)b * TT + t) * DD + kq);
    float4 mv = *(const float4*)(mask + ((size_t)t * BB + b) * DD + kq);
    float a0 = dv.x * mv.x * SCL, a1 = dv.y * mv.y * SCL;
    float a2 = dv.z * mv.z * SCL, a3 = dv.w * mv.w * SCL;
    uint32_t h01 = pkh(a0, a1), h23 = pkh(a2, a3);
    float q0 = a0 - lo_h(h01), q1 = a1 - hi_h(h01);
    float q2 = a2 - lo_h(h23), q3 = a3 - hi_h(h23);
    uint32_t m01 = pkh(q0, q1), m23 = pkh(q2, q3);
    float w0 = q0 - lo_h(m01), w1 = q1 - hi_h(m01);
    float w2 = q2 - lo_h(m23), w3 = q3 - hi_h(m23);
    uint32_t l01 = pkh(w0, w1), l23 = pkh(w2, w3);
    size_t o = (size_t)r * DD + kq;
    *(uint2*)(g_As[0] + o) = make_uint2(h01, h23);
    *(uint2*)(g_As[1] + o) = make_uint2(m01, m23);
    *(uint2*)(g_As[2] + o) = make_uint2(l01, l23);
}

// ---------------- FP16x6 split GEMM, 2 CTAs/SM -------------------------------
// Y[r][n] = 2^-24 * sum_k A'[r][k]*W'[n][k]; CTA 64x64, K-chunk 64, dbl-buffered.
// Products: a1b1 -> C1; {a2b1, a3b1, a1b2, a2b2, a1b3} -> C2.
// Dropped a2b3/a3b2/a3b3 <= 2^-33|ab| (worst correlated ~9e-9: below noise).
#define TILE_L 8192    // 64 rows x 128B per limb
#define BUF_SZ (6 * TILE_L)                  // 49152
#define SMEM_DYN (1024 + 2 * BUF_SZ)

__global__ __launch_bounds__(256, 2) void k_gemm() {
    extern __shared__ char smem[];
    const uint32_t s0 = smem_u32(smem);
    const uint32_t base = (s0 + 1023u) & ~1023u;

    const int tid = threadIdx.x;
    const int wid = tid >> 5;
    const int lane = tid & 31;

    const int n0 = blockIdx.x * 64;
    const int r0 = blockIdx.y * 64;

    // staging coords: 64 rows x 128B per limb; thread -> (row, 32B segment)
    const int srow = tid >> 2;
    const uint32_t soffb = (uint32_t)((tid & 3) * 32);
    const uint32_t srowb = (uint32_t)srow * 128u;

    const __half* aptr[3];
    const __half* wptr[3];
    #pragma unroll
    for (int s = 0; s < 3; s++) {
        aptr[s] = g_As[s] + (size_t)(r0 + srow) * DD + (soffb >> 1);
        wptr[s] = g_W1s[s] + (size_t)(n0 + srow) * DD + (soffb >> 1);
    }

#define STAGE(kt, buf)                                                          \
    do {                                                                        \
        uint32_t bb = base + (buf) * BUF_SZ;                                    \
        _Pragma("unroll")                                                       \
        for (int s = 0; s < 3; s++) {                                           \
            _Pragma("unroll")                                                   \
            for (int j = 0; j < 2; j++) {                                       \
                uint32_t ob = soffb + j * 16;                                   \
                cp16(bb + s * TILE_L + SWZ128(srowb + ob),                      \
                     aptr[s] + (kt) + j * 8);                                   \
                cp16(bb + (3 + s) * TILE_L + SWZ128(srowb + ob),                \
                     wptr[s] + (kt) + j * 8);                                   \
            }                                                                   \
        }                                                                       \
    } while (0)

    // warp tile + ldmatrix lane bases
    const int wm0 = (wid & 3) * 16;
    const int wn0 = (wid >> 2) * 32;
    const uint32_t a_row = (uint32_t)(wm0 + (lane & 15));
    const uint32_t a_koff = (uint32_t)((lane >> 4) * 8);
    const uint32_t b_row = (uint32_t)(wn0 + ((lane >> 4) << 3) + (lane & 7));
    const uint32_t b_koff = (uint32_t)(((lane >> 3) & 1) * 8);

    float C1[4][4], C2[4][4];
    #pragma unroll
    for (int nf = 0; nf < 4; nf++)
        #pragma unroll
        for (int q = 0; q < 4; q++) { C1[nf][q] = 0.f; C2[nf][q] = 0.f; }

    STAGE(0, 0);
    CP_COMMIT();

    #pragma unroll
    for (int c = 0; c < 8; c++) {
        const int buf = c & 1;
        if (c < 7) {
            STAGE((c + 1) * 64, buf ^ 1);
            CP_COMMIT();
            CP_WAIT(1);
        } else {
            CP_WAIT(0);
        }
        __syncthreads();

        const uint32_t ab = base + buf * BUF_SZ;
        const uint32_t wb = ab + 3 * TILE_L;
        #pragma unroll
        for (int kk = 0; kk < 4; kk++) {
            uint32_t Af[3][4];
            #pragma unroll
            for (int s = 0; s < 3; s++)
                ldsm_x4(Af[s], ab + s * TILE_L +
                        SWZ128(a_row * 128u + (kk * 16 + a_koff) * 2u));

#define BLOAD(sb, Bf)                                                           \
            _Pragma("unroll")                                                   \
            for (int g = 0; g < 2; g++)                                         \
                ldsm_x4(Bf[g], wb + (sb) * TILE_L +                             \
                        SWZ128((b_row + g * 16) * 128u + (kk * 16 + b_koff) * 2u))
#define PROD(sa, Bf, Cc)                                                        \
            _Pragma("unroll")                                                   \
            for (int g = 0; g < 2; g++) {                                       \
                mma16816(Cc[g * 2],     Af[sa], Bf[g][0], Bf[g][1]);            \
                mma16816(Cc[g * 2 + 1], Af[sa], Bf[g][2], Bf[g][3]);            \
            }
            {   // b1: pairs with a1 (->C1), a2, a3
                uint32_t Bf[2][4];
                BLOAD(0, Bf);
                PROD(0, Bf, C1); PROD(1, Bf, C2); PROD(2, Bf, C2);
            }
            {   // b2: pairs with a1, a2
                uint32_t Bf[2][4];
                BLOAD(1, Bf);
                PROD(0, Bf, C2); PROD(1, Bf, C2);
            }
            {   // b3: pairs with a1
                uint32_t Bf[2][4];
                BLOAD(2, Bf);
                PROD(0, Bf, C2);
            }
#undef PROD
#undef BLOAD
        }
        __syncthreads();
    }

    // epilogue: y = (C1 + C2) * 2^-24  (power-of-two descale: exact)
    {
        int rbase = r0 + wm0 + (lane >> 2);
        #pragma unroll
        for (int nf = 0; nf < 4; nf++) {
            int col = n0 + wn0 + nf * 8 + (lane & 3) * 2;
            *(float2*)(g_Y + (size_t)rbase * DD + col) =
                make_float2((C1[nf][0] + C2[nf][0]) * DSCL,
                            (C1[nf][1] + C2[nf][1]) * DSCL);
            *(float2*)(g_Y + (size_t)(rbase + 8) * DD + col) =
                make_float2((C1[nf][2] + C2[nf][2]) * DSCL,
                            (C1[nf][3] + C2[nf][3]) * DSCL);
        }
    }
}

// ---------------- BN stats: one block per t (bit-identical numerics) --------
__global__ __launch_bounds__(512) void k_stats() {
    int t = blockIdx.x;           // 0..127
    int d = threadIdx.x;          // 0..511
    const float* col = g_Y + (size_t)t * BB * DD + d;
    float s = 0.f;
    for (int b = 0; b < BB; b++) s += col[(size_t)b * DD];
    float mean = s * (1.0f / BB);
    float v = 0.f;
    for (int b = 0; b < BB; b++) {
        float x = col[(size_t)b * DD] - mean;
        v += x * x;
    }
    float vpe = v * (1.0f / BB) + 1e-5f;
    g_mean[t * DD + d] = mean;
    g_rstd[t * DD + d] = (float)(1.0 / sqrt((double)vpe));
}

// ---------------- layer-1 membrane scan ----------------
__global__ void k_scan1(const float* __restrict__ gamma,
                        const float* __restrict__ beta) {
    int id = blockIdx.x * 256 + threadIdx.x;  // b*512 + d
    int b = id >> 9, d = id & 511;
    int lane = threadIdx.x & 31;
    float g = gamma[d], be = beta[d];
    float mem = 0.f, spk = 0.f;
    const float* yp = g_Y + (size_t)b * DD + d;
    unsigned* sp = g_spk + (size_t)b * 16 + (d >> 5);
    for (int t0 = 0; t0 < TT; t0 += 8) {
        float y[8], mn[8], rs[8];
        #pragma unroll
        for (int i = 0; i < 8; i++) {
            y[i]  = yp[(size_t)(t0 + i) * BB * DD];
            mn[i] = g_mean[(t0 + i) * DD + d];
            rs[i] = g_rstd[(t0 + i) * DD + d];
        }
        #pragma unroll
        for (int i = 0; i < 8; i++) {
            float cur = g * (y[i] - mn[i]) * rs[i] + be;
            mem = 0.5f * mem + cur - spk;
            spk = (mem - 1.0f) > 0.f ? 1.0f : 0.0f;
            unsigned bal = __ballot_sync(0xffffffffu, spk != 0.f);
            if (lane == 0) sp[(size_t)(t0 + i) * BB * 16] = bal;
        }
    }
}

// ---------------- layer 2: cur2 = spk1 @ W2^T + b2 ----------------
__global__ __launch_bounds__(256) void k_layer2(const float* __restrict__ W2,
                                                const float* __restrict__ b2) {
    int r = blockIdx.x * 8 + (threadIdx.x >> 5);
    int lane = threadIdx.x & 31;
    const unsigned* sp = g_spk + (size_t)r * 16;
    float acc[10];
    #pragma unroll
    for (int o = 0; o < 10; o++) acc[o] = 0.f;
    #pragma unroll
    for (int j = 0; j < 16; j++) {
        unsigned w = sp[j];
        float s = ((w >> lane) & 1u) ? 1.0f : 0.0f;
        int d = j * 32 + lane;
        #pragma unroll
        for (int o = 0; o < 10; o++) acc[o] += s * W2[o * DD + d];
    }
    #pragma unroll
    for (int o = 0; o < 10; o++) {
        #pragma unroll
        for (int off = 16; off; off >>= 1)
            acc[o] += __shfl_xor_sync(0xffffffffu, acc[o], off);
    }
    if (lane == 0) {
        float* out = g_cur2 + (size_t)r * 10;
        #pragma unroll
        for (int o = 0; o < 10; o++) out[o] = acc[o] + b2[o];
    }
}

// ---------------- layer-2 membrane scan + output ----------------
__global__ void k_scan2(float* __restrict__ out) {
    int id = blockIdx.x * 256 + threadIdx.x;
    if (id >= BB * OO) return;
    int b = id / 10, o = id - b * 10;
    float mem = 0.f, spk = 0.f;
    for (int t = 0; t < TT; t++) {
        float c = g_cur2[((size_t)t * BB + b) * 10 + o];
        mem = 0.5f * mem + c - spk;
        spk = (mem - 1.0f) > 0.f ? 1.0f : 0.0f;
        out[((size_t)t * BB + b) * 10 + o] = spk;
    }
}

extern "C" void kernel_launch(void* const* d_in, const int* in_sizes, int n_in,
                              void* d_out, int out_size) {
    const float* data  = (const float*)d_in[0];  // [B,T,D]
    const float* mask  = (const float*)d_in[1];  // [T,B,D]
    const float* W1    = (const float*)d_in[2];  // [D,D]
    // d_in[3] = b1: cancels exactly under BatchNorm mean subtraction
    const float* gamma = (const float*)d_in[4];
    const float* beta  = (const float*)d_in[5];
    const float* W2    = (const float*)d_in[6];  // [O,D]
    const float* b2    = (const float*)d_in[7];
    float* out = (float*)d_out;                  // [T,B,O]

    cudaFuncSetAttribute(k_gemm, cudaFuncAttributeMaxDynamicSharedMemorySize, SMEM_DYN);

    // k_gemm kept as the 4th launch (ncu capture slot).
    k_split<<<1024, 256>>>(W1);
    k_convA<<<16384, 256>>>(data, mask, 0);
    k_convA<<<16384, 256>>>(data, mask, 16384 * 256);
    k_gemm<<<dim3(8, 1024), 256, SMEM_DYN>>>();
    k_stats<<<128, 512>>>();
    k_scan1<<<1024, 256>>>(gamma, beta);
    k_layer2<<<8192, 256>>>(W2, b2);
    k_scan2<<<20, 256>>>(out);
}

// round 8
// speedup vs baseline: 2.3239x; 1.3208x over previous
#include <cuda_runtime.h>
#include <cuda_fp16.h>
#include <cstdint>

#define TT 128
#define BB 512
#define DD 512
#define OO 10

#define SCL 4096.0f                 // 2^12 operand scale (exact)
#define DSCL 5.9604644775390625e-8f // 2^-24 descale (exact)

// ---------------- device scratch ----------------
static __device__ float     g_Y[TT * BB * DD];       // cur1 pre-BN [t][b][d]
static __device__ __half    g_W1s[2][DD * DD];       // W1*2^12 fp16 limbs, [n][k]
static __device__ __half    g_As[2][TT * BB * DD];   // (mask*data)*2^12 limbs
static __device__ float     g_mean[TT * DD];
static __device__ float     g_rstd[TT * DD];
static __device__ unsigned  g_spk[TT * BB * (DD / 32)];
static __device__ float     g_cur2[TT * BB * OO];

// ---------------- helpers ----------------
__device__ __forceinline__ uint32_t smem_u32(const void* p) {
    uint32_t a;
    asm("{ .reg .u64 t; cvta.to.shared.u64 t, %1; cvt.u32.u64 %0, t; }"
        : "=r"(a) : "l"(p));
    return a;
}
#define SWZ128(off) ((off) ^ (((off) >> 3) & 0x70))

__device__ __forceinline__ void cp16(uint32_t dst, const void* src) {
    asm volatile("cp.async.cg.shared.global [%0], [%1], 16;"
                 :: "r"(dst), "l"(src) : "memory");
}
#define CP_COMMIT() asm volatile("cp.async.commit_group;" ::: "memory")
#define CP_WAIT(n)  asm volatile("cp.async.wait_group %0;" :: "n"(n) : "memory")

__device__ __forceinline__ void ldsm_x4(uint32_t* r, uint32_t addr) {
    asm volatile("ldmatrix.sync.aligned.m8n8.x4.shared.b16 {%0,%1,%2,%3}, [%4];"
                 : "=r"(r[0]), "=r"(r[1]), "=r"(r[2]), "=r"(r[3]) : "r"(addr));
}
__device__ __forceinline__ void mma16816(float* c, const uint32_t* a,
                                         uint32_t b0, uint32_t b1) {
    asm volatile(
        "mma.sync.aligned.m16n8k16.row.col.f32.f16.f16.f32 "
        "{%0,%1,%2,%3}, {%4,%5,%6,%7}, {%8,%9}, {%0,%1,%2,%3};"
        : "+f"(c[0]), "+f"(c[1]), "+f"(c[2]), "+f"(c[3])
        : "r"(a[0]), "r"(a[1]), "r"(a[2]), "r"(a[3]), "r"(b0), "r"(b1));
}

// pack two floats -> half2 (RN); unpack halves
__device__ __forceinline__ uint32_t pkh(float lo, float hi) {
    __half2 h = __floats2half2_rn(lo, hi);
    return *(uint32_t*)&h;
}
__device__ __forceinline__ float lo_h(uint32_t v) {
    __half2 h = *(__half2*)&v; return __low2float(h);
}
__device__ __forceinline__ float hi_h(uint32_t v) {
    __half2 h = *(__half2*)&v; return __high2float(h);
}

// ---------------- W1*2^12 -> 2 fp16 limbs (RN: residual <= 2^-24|w|) --------
__global__ void k_split(const float* __restrict__ W1) {
    int i = blockIdx.x * 256 + threadIdx.x;  // 262144
    float a = W1[i] * SCL;
    __half h = __float2half_rn(a);
    float r1 = a - __half2float(h);
    __half m = __float2half_rn(r1);
    g_W1s[0][i] = h; g_W1s[1][i] = m;
}

// ---------------- A = (mask*data)*2^12 -> 2 fp16 limbs (two launches) -------
__global__ void k_convA(const float* __restrict__ data,
                        const float* __restrict__ mask, int base_id) {
    int id = base_id + blockIdx.x * 256 + threadIdx.x;
    int r = id >> 7;                            // row = t*512 + b
    int kq = (id & 127) * 4;
    int t = r >> 9, b = r & 511;
    float4 dv = *(const float4*)(data + ((size_t)b * TT + t) * DD + kq);
    float4 mv = *(const float4*)(mask + ((size_t)t * BB + b) * DD + kq);
    float a0 = dv.x * mv.x * SCL, a1 = dv.y * mv.y * SCL;
    float a2 = dv.z * mv.z * SCL, a3 = dv.w * mv.w * SCL;
    uint32_t h01 = pkh(a0, a1), h23 = pkh(a2, a3);
    float q0 = a0 - lo_h(h01), q1 = a1 - hi_h(h01);
    float q2 = a2 - lo_h(h23), q3 = a3 - hi_h(h23);
    uint32_t m01 = pkh(q0, q1), m23 = pkh(q2, q3);
    size_t o = (size_t)r * DD + kq;
    *(uint2*)(g_As[0] + o) = make_uint2(h01, h23);
    *(uint2*)(g_As[1] + o) = make_uint2(m01, m23);
}

// ---------------- FP16x4 split GEMM, single-sync pipeline --------------------
// Y[r][n] = 2^-24 * sum_k A'[r][k]*W'[n][k]; CTA 64x64, K-chunk 64, dbl-buffered.
// Products: a1b1 -> C1; {a2b1, a1b2, a2b2} -> C2. Split residual ~5e-8 rel Y,
// far below the proven-flip-free fp32 reorder noise (~7e-7).
#define TILE_L 8192    // 64 rows x 128B per limb
#define BUF_SZ (4 * TILE_L)                  // 32768
#define SMEM_DYN (1024 + 2 * BUF_SZ)

__global__ __launch_bounds__(256, 2) void k_gemm() {
    extern __shared__ char smem[];
    const uint32_t s0 = smem_u32(smem);
    const uint32_t base = (s0 + 1023u) & ~1023u;

    const int tid = threadIdx.x;
    const int wid = tid >> 5;
    const int lane = tid & 31;

    const int n0 = blockIdx.x * 64;
    const int r0 = blockIdx.y * 64;

    // staging coords: 64 rows x 128B per limb; thread -> (row, 32B segment)
    const int srow = tid >> 2;
    const uint32_t soffb = (uint32_t)((tid & 3) * 32);
    const uint32_t srowb = (uint32_t)srow * 128u;

    const __half* aptr[2];
    const __half* wptr[2];
    #pragma unroll
    for (int s = 0; s < 2; s++) {
        aptr[s] = g_As[s] + (size_t)(r0 + srow) * DD + (soffb >> 1);
        wptr[s] = g_W1s[s] + (size_t)(n0 + srow) * DD + (soffb >> 1);
    }

#define STAGE(kt, buf)                                                          \
    do {                                                                        \
        uint32_t bb = base + (buf) * BUF_SZ;                                    \
        _Pragma("unroll")                                                       \
        for (int s = 0; s < 2; s++) {                                           \
            _Pragma("unroll")                                                   \
            for (int j = 0; j < 2; j++) {                                       \
                uint32_t ob = soffb + j * 16;                                   \
                cp16(bb + s * TILE_L + SWZ128(srowb + ob),                      \
                     aptr[s] + (kt) + j * 8);                                   \
                cp16(bb + (2 + s) * TILE_L + SWZ128(srowb + ob),                \
                     wptr[s] + (kt) + j * 8);                                   \
            }                                                                   \
        }                                                                       \
    } while (0)

    // warp tile + ldmatrix lane bases
    const int wm0 = (wid & 3) * 16;
    const int wn0 = (wid >> 2) * 32;
    const uint32_t a_row = (uint32_t)(wm0 + (lane & 15));
    const uint32_t a_koff = (uint32_t)((lane >> 4) * 8);
    const uint32_t b_row = (uint32_t)(wn0 + ((lane >> 4) << 3) + (lane & 7));
    const uint32_t b_koff = (uint32_t)(((lane >> 3) & 1) * 8);

    float C1[4][4], C2[4][4];
    #pragma unroll
    for (int nf = 0; nf < 4; nf++)
        #pragma unroll
        for (int q = 0; q < 4; q++) { C1[nf][q] = 0.f; C2[nf][q] = 0.f; }

    STAGE(0, 0);
    CP_COMMIT();

    #pragma unroll
    for (int c = 0; c < 8; c++) {
        const int buf = c & 1;
        CP_WAIT(0);              // buf's data landed (only pending group)
        __syncthreads();         // visibility + prev-compute done (WAR on buf^1)
        if (c < 7) {
            STAGE((c + 1) * 64, buf ^ 1);
            CP_COMMIT();
        }

        const uint32_t ab = base + buf * BUF_SZ;
        const uint32_t wb = ab + 2 * TILE_L;
        #pragma unroll
        for (int kk = 0; kk < 4; kk++) {
            uint32_t Af[2][4];
            #pragma unroll
            for (int s = 0; s < 2; s++)
                ldsm_x4(Af[s], ab + s * TILE_L +
                        SWZ128(a_row * 128u + (kk * 16 + a_koff) * 2u));

#define BLOAD(sb, Bf)                                                           \
            _Pragma("unroll")                                                   \
            for (int g = 0; g < 2; g++)                                         \
                ldsm_x4(Bf[g], wb + (sb) * TILE_L +                             \
                        SWZ128((b_row + g * 16) * 128u + (kk * 16 + b_koff) * 2u))
#define PROD(sa, Bf, Cc)                                                        \
            _Pragma("unroll")                                                   \
            for (int g = 0; g < 2; g++) {                                       \
                mma16816(Cc[g * 2],     Af[sa], Bf[g][0], Bf[g][1]);            \
                mma16816(Cc[g * 2 + 1], Af[sa], Bf[g][2], Bf[g][3]);            \
            }
            {   // b1: a1b1 -> C1, a2b1 -> C2
                uint32_t Bf[2][4];
                BLOAD(0, Bf);
                PROD(0, Bf, C1); PROD(1, Bf, C2);
            }
            {   // b2: a1b2 -> C2, a2b2 -> C2
                uint32_t Bf[2][4];
                BLOAD(1, Bf);
                PROD(0, Bf, C2); PROD(1, Bf, C2);
            }
#undef PROD
#undef BLOAD
        }
    }

    // epilogue: y = (C1 + C2) * 2^-24  (power-of-two descale: exact)
    {
        int rbase = r0 + wm0 + (lane >> 2);
        #pragma unroll
        for (int nf = 0; nf < 4; nf++) {
            int col = n0 + wn0 + nf * 8 + (lane & 3) * 2;
            *(float2*)(g_Y + (size_t)rbase * DD + col) =
                make_float2((C1[nf][0] + C2[nf][0]) * DSCL,
                            (C1[nf][1] + C2[nf][1]) * DSCL);
            *(float2*)(g_Y + (size_t)(rbase + 8) * DD + col) =
                make_float2((C1[nf][2] + C2[nf][2]) * DSCL,
                            (C1[nf][3] + C2[nf][3]) * DSCL);
        }
    }
}

// ---------------- BN stats: one block per t (unchanged numerics) ------------
__global__ __launch_bounds__(512) void k_stats() {
    int t = blockIdx.x;           // 0..127
    int d = threadIdx.x;          // 0..511
    const float* col = g_Y + (size_t)t * BB * DD + d;
    float s = 0.f;
    for (int b = 0; b < BB; b++) s += col[(size_t)b * DD];
    float mean = s * (1.0f / BB);
    float v = 0.f;
    for (int b = 0; b < BB; b++) {
        float x = col[(size_t)b * DD] - mean;
        v += x * x;
    }
    float vpe = v * (1.0f / BB) + 1e-5f;
    g_mean[t * DD + d] = mean;
    g_rstd[t * DD + d] = (float)(1.0 / sqrt((double)vpe));
}

// ---------------- layer-1 membrane scan ----------------
__global__ void k_scan1(const float* __restrict__ gamma,
                        const float* __restrict__ beta) {
    int id = blockIdx.x * 256 + threadIdx.x;  // b*512 + d
    int b = id >> 9, d = id & 511;
    int lane = threadIdx.x & 31;
    float g = gamma[d], be = beta[d];
    float mem = 0.f, spk = 0.f;
    const float* yp = g_Y + (size_t)b * DD + d;
    unsigned* sp = g_spk + (size_t)b * 16 + (d >> 5);
    for (int t0 = 0; t0 < TT; t0 += 8) {
        float y[8], mn[8], rs[8];
        #pragma unroll
        for (int i = 0; i < 8; i++) {
            y[i]  = yp[(size_t)(t0 + i) * BB * DD];
            mn[i] = g_mean[(t0 + i) * DD + d];
            rs[i] = g_rstd[(t0 + i) * DD + d];
        }
        #pragma unroll
        for (int i = 0; i < 8; i++) {
            float cur = g * (y[i] - mn[i]) * rs[i] + be;
            mem = 0.5f * mem + cur - spk;
            spk = (mem - 1.0f) > 0.f ? 1.0f : 0.0f;
            unsigned bal = __ballot_sync(0xffffffffu, spk != 0.f);
            if (lane == 0) sp[(size_t)(t0 + i) * BB * 16] = bal;
        }
    }
}

// ---------------- layer 2: cur2 = spk1 @ W2^T + b2 ----------------
__global__ __launch_bounds__(256) void k_layer2(const float* __restrict__ W2,
                                                const float* __restrict__ b2) {
    int r = blockIdx.x * 8 + (threadIdx.x >> 5);
    int lane = threadIdx.x & 31;
    const unsigned* sp = g_spk + (size_t)r * 16;
    float acc[10];
    #pragma unroll
    for (int o = 0; o < 10; o++) acc[o] = 0.f;
    #pragma unroll
    for (int j = 0; j < 16; j++) {
        unsigned w = sp[j];
        float s = ((w >> lane) & 1u) ? 1.0f : 0.0f;
        int d = j * 32 + lane;
        #pragma unroll
        for (int o = 0; o < 10; o++) acc[o] += s * W2[o * DD + d];
    }
    #pragma unroll
    for (int o = 0; o < 10; o++) {
        #pragma unroll
        for (int off = 16; off; off >>= 1)
            acc[o] += __shfl_xor_sync(0xffffffffu, acc[o], off);
    }
    if (lane == 0) {
        float* out = g_cur2 + (size_t)r * 10;
        #pragma unroll
        for (int o = 0; o < 10; o++) out[o] = acc[o] + b2[o];
    }
}

// ---------------- layer-2 membrane scan + output ----------------
__global__ void k_scan2(float* __restrict__ out) {
    int id = blockIdx.x * 256 + threadIdx.x;
    if (id >= BB * OO) return;
    int b = id / 10, o = id - b * 10;
    float mem = 0.f, spk = 0.f;
    for (int t = 0; t < TT; t++) {
        float c = g_cur2[((size_t)t * BB + b) * 10 + o];
        mem = 0.5f * mem + c - spk;
        spk = (mem - 1.0f) > 0.f ? 1.0f : 0.0f;
        out[((size_t)t * BB + b) * 10 + o] = spk;
    }
}

extern "C" void kernel_launch(void* const* d_in, const int* in_sizes, int n_in,
                              void* d_out, int out_size) {
    const float* data  = (const float*)d_in[0];  // [B,T,D]
    const float* mask  = (const float*)d_in[1];  // [T,B,D]
    const float* W1    = (const float*)d_in[2];  // [D,D]
    // d_in[3] = b1: cancels exactly under BatchNorm mean subtraction
    const float* gamma = (const float*)d_in[4];
    const float* beta  = (const float*)d_in[5];
    const float* W2    = (const float*)d_in[6];  // [O,D]
    const float* b2    = (const float*)d_in[7];
    float* out = (float*)d_out;                  // [T,B,O]

    cudaFuncSetAttribute(k_gemm, cudaFuncAttributeMaxDynamicSharedMemorySize, SMEM_DYN);

    // k_gemm kept as the 4th launch (ncu capture slot).
    k_split<<<1024, 256>>>(W1);
    k_convA<<<16384, 256>>>(data, mask, 0);
    k_convA<<<16384, 256>>>(data, mask, 16384 * 256);
    k_gemm<<<dim3(8, 1024), 256, SMEM_DYN>>>();
    k_stats<<<128, 512>>>();
    k_scan1<<<1024, 256>>>(gamma, beta);
    k_layer2<<<8192, 256>>>(W2, b2);
    k_scan2<<<20, 256>>>(out);
}

// round 9
// speedup vs baseline: 2.4029x; 1.0340x over previous
#include <cuda_runtime.h>
#include <cuda_fp16.h>
#include <cstdint>

#define TT 128
#define BB 512
#define DD 512
#define OO 10

#define SCL 4096.0f                 // 2^12 operand scale (exact)
#define DSCL 5.9604644775390625e-8f // 2^-24 descale (exact)

// ---------------- device scratch ----------------
static __device__ float     g_Y[TT * BB * DD];       // cur1 pre-BN [t][b][d]
static __device__ __half    g_W1s[2][DD * DD];       // W1*2^12 fp16 limbs, [n][k]
static __device__ __half    g_As[2][TT * BB * DD];   // (mask*data)*2^12 limbs
static __device__ float     g_mean[TT * DD];
static __device__ float     g_rstd[TT * DD];
static __device__ unsigned  g_spk[TT * BB * (DD / 32)];
static __device__ float     g_cur2[TT * BB * OO];
static __device__ float     g_W2p[DD][12];           // W2 transposed+padded (layer2)

// ---------------- helpers ----------------
__device__ __forceinline__ uint32_t smem_u32(const void* p) {
    uint32_t a;
    asm("{ .reg .u64 t; cvta.to.shared.u64 t, %1; cvt.u32.u64 %0, t; }"
        : "=r"(a) : "l"(p));
    return a;
}
#define SWZ128(off) ((off) ^ (((off) >> 3) & 0x70))

__device__ __forceinline__ void cp16(uint32_t dst, const void* src) {
    asm volatile("cp.async.cg.shared.global [%0], [%1], 16;"
                 :: "r"(dst), "l"(src) : "memory");
}
#define CP_COMMIT() asm volatile("cp.async.commit_group;" ::: "memory")
#define CP_WAIT(n)  asm volatile("cp.async.wait_group %0;" :: "n"(n) : "memory")

__device__ __forceinline__ void ldsm_x4(uint32_t* r, uint32_t addr) {
    asm volatile("ldmatrix.sync.aligned.m8n8.x4.shared.b16 {%0,%1,%2,%3}, [%4];"
                 : "=r"(r[0]), "=r"(r[1]), "=r"(r[2]), "=r"(r[3]) : "r"(addr));
}
__device__ __forceinline__ void mma16816(float* c, const uint32_t* a,
                                         uint32_t b0, uint32_t b1) {
    asm volatile(
        "mma.sync.aligned.m16n8k16.row.col.f32.f16.f16.f32 "
        "{%0,%1,%2,%3}, {%4,%5,%6,%7}, {%8,%9}, {%0,%1,%2,%3};"
        : "+f"(c[0]), "+f"(c[1]), "+f"(c[2]), "+f"(c[3])
        : "r"(a[0]), "r"(a[1]), "r"(a[2]), "r"(a[3]), "r"(b0), "r"(b1));
}

// pack two floats -> half2 (RN); unpack halves
__device__ __forceinline__ uint32_t pkh(float lo, float hi) {
    __half2 h = __floats2half2_rn(lo, hi);
    return *(uint32_t*)&h;
}
__device__ __forceinline__ float lo_h(uint32_t v) {
    __half2 h = *(__half2*)&v; return __low2float(h);
}
__device__ __forceinline__ float hi_h(uint32_t v) {
    __half2 h = *(__half2*)&v; return __high2float(h);
}

// ---------------- W1*2^12 -> 2 fp16 limbs ----------------
__global__ void k_split(const float* __restrict__ W1) {
    int i = blockIdx.x * 256 + threadIdx.x;  // 262144
    float a = W1[i] * SCL;
    __half h = __float2half_rn(a);
    float r1 = a - __half2float(h);
    __half m = __float2half_rn(r1);
    g_W1s[0][i] = h; g_W1s[1][i] = m;
}

// ---------------- A = (mask*data)*2^12 -> 2 fp16 limbs (two launches) -------
__global__ void k_convA(const float* __restrict__ data,
                        const float* __restrict__ mask, int base_id) {
    int id = base_id + blockIdx.x * 256 + threadIdx.x;
    int r = id >> 7;                            // row = t*512 + b
    int kq = (id & 127) * 4;
    int t = r >> 9, b = r & 511;
    float4 dv = *(const float4*)(data + ((size_t)b * TT + t) * DD + kq);
    float4 mv = *(const float4*)(mask + ((size_t)t * BB + b) * DD + kq);
    float a0 = dv.x * mv.x * SCL, a1 = dv.y * mv.y * SCL;
    float a2 = dv.z * mv.z * SCL, a3 = dv.w * mv.w * SCL;
    uint32_t h01 = pkh(a0, a1), h23 = pkh(a2, a3);
    float q0 = a0 - lo_h(h01), q1 = a1 - hi_h(h01);
    float q2 = a2 - lo_h(h23), q3 = a3 - hi_h(h23);
    uint32_t m01 = pkh(q0, q1), m23 = pkh(q2, q3);
    size_t o = (size_t)r * DD + kq;
    *(uint2*)(g_As[0] + o) = make_uint2(h01, h23);
    *(uint2*)(g_As[1] + o) = make_uint2(m01, m23);
}

// ---------------- FP16x3 split GEMM --------------------------------------
// Y[r][n] = 2^-24 * sum_k A'[r][k]*W'[n][k]; CTA 64x64, K-chunk 64, dbl-buffered.
// Products: a1b1 -> C1; {a2b1, a1b2} -> C2. Dropped a2b2: RN-residual product,
// typical ~3e-8 abs (5σ ~1.5e-7) vs Y~1.4 — below proven-flip-free noise.
#define TILE_L 8192    // 64 rows x 128B per limb
#define BUF_SZ (4 * TILE_L)                  // 32768
#define SMEM_DYN (1024 + 2 * BUF_SZ)

__global__ __launch_bounds__(256, 2) void k_gemm() {
    extern __shared__ char smem[];
    const uint32_t s0 = smem_u32(smem);
    const uint32_t base = (s0 + 1023u) & ~1023u;

    const int tid = threadIdx.x;
    const int wid = tid >> 5;
    const int lane = tid & 31;

    const int n0 = blockIdx.x * 64;
    const int r0 = blockIdx.y * 64;

    // staging coords: 64 rows x 128B per limb; thread -> (row, 32B segment)
    const int srow = tid >> 2;
    const uint32_t soffb = (uint32_t)((tid & 3) * 32);
    const uint32_t srowb = (uint32_t)srow * 128u;

    const __half* aptr[2];
    const __half* wptr[2];
    #pragma unroll
    for (int s = 0; s < 2; s++) {
        aptr[s] = g_As[s] + (size_t)(r0 + srow) * DD + (soffb >> 1);
        wptr[s] = g_W1s[s] + (size_t)(n0 + srow) * DD + (soffb >> 1);
    }

#define STAGE(kt, buf)                                                          \
    do {                                                                        \
        uint32_t bb = base + (buf) * BUF_SZ;                                    \
        _Pragma("unroll")                                                       \
        for (int s = 0; s < 2; s++) {                                           \
            _Pragma("unroll")                                                   \
            for (int j = 0; j < 2; j++) {                                       \
                uint32_t ob = soffb + j * 16;                                   \
                cp16(bb + s * TILE_L + SWZ128(srowb + ob),                      \
                     aptr[s] + (kt) + j * 8);                                   \
                cp16(bb + (2 + s) * TILE_L + SWZ128(srowb + ob),                \
                     wptr[s] + (kt) + j * 8);                                   \
            }                                                                   \
        }                                                                       \
    } while (0)

    // warp tile + ldmatrix lane bases
    const int wm0 = (wid & 3) * 16;
    const int wn0 = (wid >> 2) * 32;
    const uint32_t a_row = (uint32_t)(wm0 + (lane & 15));
    const uint32_t a_koff = (uint32_t)((lane >> 4) * 8);
    const uint32_t b_row = (uint32_t)(wn0 + ((lane >> 4) << 3) + (lane & 7));
    const uint32_t b_koff = (uint32_t)(((lane >> 3) & 1) * 8);

    float C1[4][4], C2[4][4];
    #pragma unroll
    for (int nf = 0; nf < 4; nf++)
        #pragma unroll
        for (int q = 0; q < 4; q++) { C1[nf][q] = 0.f; C2[nf][q] = 0.f; }

    STAGE(0, 0);
    CP_COMMIT();

    #pragma unroll
    for (int c = 0; c < 8; c++) {
        const int buf = c & 1;
        CP_WAIT(0);              // buf's data landed (only pending group)
        __syncthreads();         // visibility + WAR on buf^1
        if (c < 7) {
            STAGE((c + 1) * 64, buf ^ 1);
            CP_COMMIT();
        }

        const uint32_t ab = base + buf * BUF_SZ;
        const uint32_t wb = ab + 2 * TILE_L;
        #pragma unroll
        for (int kk = 0; kk < 4; kk++) {
            uint32_t Af[2][4];
            #pragma unroll
            for (int s = 0; s < 2; s++)
                ldsm_x4(Af[s], ab + s * TILE_L +
                        SWZ128(a_row * 128u + (kk * 16 + a_koff) * 2u));

#define BLOAD(sb, Bf)                                                           \
            _Pragma("unroll")                                                   \
            for (int g = 0; g < 2; g++)                                         \
                ldsm_x4(Bf[g], wb + (sb) * TILE_L +                             \
                        SWZ128((b_row + g * 16) * 128u + (kk * 16 + b_koff) * 2u))
#define PROD(sa, Bf, Cc)                                                        \
            _Pragma("unroll")                                                   \
            for (int g = 0; g < 2; g++) {                                       \
                mma16816(Cc[g * 2],     Af[sa], Bf[g][0], Bf[g][1]);            \
                mma16816(Cc[g * 2 + 1], Af[sa], Bf[g][2], Bf[g][3]);            \
            }
            {   // b1: a1b1 -> C1, a2b1 -> C2
                uint32_t Bf[2][4];
                BLOAD(0, Bf);
                PROD(0, Bf, C1); PROD(1, Bf, C2);
            }
            {   // b2: a1b2 -> C2  (a2b2 dropped)
                uint32_t Bf[2][4];
                BLOAD(1, Bf);
                PROD(0, Bf, C2);
            }
#undef PROD
#undef BLOAD
        }
    }

    // epilogue: y = (C1 + C2) * 2^-24  (power-of-two descale: exact)
    {
        int rbase = r0 + wm0 + (lane >> 2);
        #pragma unroll
        for (int nf = 0; nf < 4; nf++) {
            int col = n0 + wn0 + nf * 8 + (lane & 3) * 2;
            *(float2*)(g_Y + (size_t)rbase * DD + col) =
                make_float2((C1[nf][0] + C2[nf][0]) * DSCL,
                            (C1[nf][1] + C2[nf][1]) * DSCL);
            *(float2*)(g_Y + (size_t)(rbase + 8) * DD + col) =
                make_float2((C1[nf][2] + C2[nf][2]) * DSCL,
                            (C1[nf][3] + C2[nf][3]) * DSCL);
        }
    }
}

// ---------------- W2 transpose+pad for layer2 (bitwise copy) ----------------
__global__ void k_prep(const float* __restrict__ W2) {
    int d = threadIdx.x;          // one block of 512
    #pragma unroll
    for (int o = 0; o < 10; o++) g_W2p[d][o] = W2[o * DD + d];
    g_W2p[d][10] = 0.f; g_W2p[d][11] = 0.f;
}

// ---------------- BN stats: one block per t (unchanged numerics) ------------
__global__ __launch_bounds__(512) void k_stats() {
    int t = blockIdx.x;           // 0..127
    int d = threadIdx.x;          // 0..511
    const float* col = g_Y + (size_t)t * BB * DD + d;
    float s = 0.f;
    for (int b = 0; b < BB; b++) s += col[(size_t)b * DD];
    float mean = s * (1.0f / BB);
    float v = 0.f;
    for (int b = 0; b < BB; b++) {
        float x = col[(size_t)b * DD] - mean;
        v += x * x;
    }
    float vpe = v * (1.0f / BB) + 1e-5f;
    g_mean[t * DD + d] = mean;
    g_rstd[t * DD + d] = (float)(1.0 / sqrt((double)vpe));
}

// ---------------- layer-1 membrane scan ----------------
__global__ void k_scan1(const float* __restrict__ gamma,
                        const float* __restrict__ beta) {
    int id = blockIdx.x * 256 + threadIdx.x;  // b*512 + d
    int b = id >> 9, d = id & 511;
    int lane = threadIdx.x & 31;
    float g = gamma[d], be = beta[d];
    float mem = 0.f, spk = 0.f;
    const float* yp = g_Y + (size_t)b * DD + d;
    unsigned* sp = g_spk + (size_t)b * 16 + (d >> 5);
    for (int t0 = 0; t0 < TT; t0 += 8) {
        float y[8], mn[8], rs[8];
        #pragma unroll
        for (int i = 0; i < 8; i++) {
            y[i]  = yp[(size_t)(t0 + i) * BB * DD];
            mn[i] = g_mean[(t0 + i) * DD + d];
            rs[i] = g_rstd[(t0 + i) * DD + d];
        }
        #pragma unroll
        for (int i = 0; i < 8; i++) {
            float cur = g * (y[i] - mn[i]) * rs[i] + be;
            mem = 0.5f * mem + cur - spk;
            spk = (mem - 1.0f) > 0.f ? 1.0f : 0.0f;
            unsigned bal = __ballot_sync(0xffffffffu, spk != 0.f);
            if (lane == 0) sp[(size_t)(t0 + i) * BB * 16] = bal;
        }
    }
}

// ---------------- layer 2: cur2 = spk1 @ W2^T + b2 ---------------------------
// Same FMA operands/order/reduction tree as rounds 1-8; only the W2 fetch is
// vectorized via the bitwise-identical transposed copy g_W2p.
__global__ __launch_bounds__(256) void k_layer2(const float* __restrict__ b2) {
    int r = blockIdx.x * 8 + (threadIdx.x >> 5);
    int lane = threadIdx.x & 31;
    const unsigned* sp = g_spk + (size_t)r * 16;
    float acc[10];
    #pragma unroll
    for (int o = 0; o < 10; o++) acc[o] = 0.f;
    #pragma unroll
    for (int j = 0; j < 16; j++) {
        unsigned w = sp[j];
        float s = ((w >> lane) & 1u) ? 1.0f : 0.0f;
        int d = j * 32 + lane;
        const float4* wp = (const float4*)g_W2p[d];
        float4 v0 = wp[0], v1 = wp[1], v2 = wp[2];
        acc[0] += s * v0.x; acc[1] += s * v0.y; acc[2] += s * v0.z; acc[3] += s * v0.w;
        acc[4] += s * v1.x; acc[5] += s * v1.y; acc[6] += s * v1.z; acc[7] += s * v1.w;
        acc[8] += s * v2.x; acc[9] += s * v2.y;
    }
    #pragma unroll
    for (int o = 0; o < 10; o++) {
        #pragma unroll
        for (int off = 16; off; off >>= 1)
            acc[o] += __shfl_xor_sync(0xffffffffu, acc[o], off);
    }
    if (lane == 0) {
        float* out = g_cur2 + (size_t)r * 10;
        #pragma unroll
        for (int o = 0; o < 10; o++) out[o] = acc[o] + b2[o];
    }
}

// ---------------- layer-2 membrane scan + output ----------------
__global__ void k_scan2(float* __restrict__ out) {
    int id = blockIdx.x * 256 + threadIdx.x;
    if (id >= BB * OO) return;
    int b = id / 10, o = id - b * 10;
    float mem = 0.f, spk = 0.f;
    for (int t = 0; t < TT; t++) {
        float c = g_cur2[((size_t)t * BB + b) * 10 + o];
        mem = 0.5f * mem + c - spk;
        spk = (mem - 1.0f) > 0.f ? 1.0f : 0.0f;
        out[((size_t)t * BB + b) * 10 + o] = spk;
    }
}

extern "C" void kernel_launch(void* const* d_in, const int* in_sizes, int n_in,
                              void* d_out, int out_size) {
    const float* data  = (const float*)d_in[0];  // [B,T,D]
    const float* mask  = (const float*)d_in[1];  // [T,B,D]
    const float* W1    = (const float*)d_in[2];  // [D,D]
    // d_in[3] = b1: cancels exactly under BatchNorm mean subtraction
    const float* gamma = (const float*)d_in[4];
    const float* beta  = (const float*)d_in[5];
    const float* W2    = (const float*)d_in[6];  // [O,D]
    const float* b2    = (const float*)d_in[7];
    float* out = (float*)d_out;                  // [T,B,O]

    cudaFuncSetAttribute(k_gemm, cudaFuncAttributeMaxDynamicSharedMemorySize, SMEM_DYN);

    // k_gemm kept as the 4th launch (ncu capture slot).
    k_split<<<1024, 256>>>(W1);
    k_convA<<<16384, 256>>>(data, mask, 0);
    k_convA<<<16384, 256>>>(data, mask, 16384 * 256);
    k_gemm<<<dim3(8, 1024), 256, SMEM_DYN>>>();
    k_prep<<<1, 512>>>(W2);
    k_stats<<<128, 512>>>();
    k_scan1<<<1024, 256>>>(gamma, beta);
    k_layer2<<<8192, 256>>>(b2);
    k_scan2<<<20, 256>>>(out);
}